// round 5
// baseline (speedup 1.0000x reference)
#include <cuda_runtime.h>

// FullAttention (causal) — B=2, L=2048, H=16, E=D=64, fp32.
// Flash-attention style: 1 thread = 1 query row. BM=128 rows per CTA,
// K/V staged in SMEM 64 keys at a time, online softmax over chunks of 16
// keys so the score array stays fully register-resident.

#define BM   128   // query rows per CTA (= blockDim.x)
#define BN   64    // keys staged in SMEM per tile
#define CH   16    // keys per register-resident softmax chunk
#define EDIM 64

#define Bz 2
#define Lz 2048
#define Hz 16

__global__ __launch_bounds__(BM) void fullattn_kernel(
    const float* __restrict__ Q, const float* __restrict__ K,
    const float* __restrict__ V, float* __restrict__ O)
{
    __shared__ float Ks[BN][EDIM];
    __shared__ float Vs[BN][EDIM];

    const int bh  = blockIdx.y;     // b*Hz + h
    const int b   = bh >> 4;
    const int h   = bh & 15;
    const int q0  = blockIdx.x * BM;
    const int row = q0 + threadIdx.x;   // this thread's global query index

    // 1/sqrt(64) * log2(e): do softmax in base-2 (MUFU.EX2 directly)
    const float qscale = 0.125f * 1.44269504088896340736f;

    // Load and pre-scale this thread's q row (64 contiguous floats)
    float4 q4[EDIM / 4];
    {
        const float4* qp =
            (const float4*)(Q + ((size_t)((b * Lz + row) * Hz + h)) * EDIM);
#pragma unroll
        for (int i = 0; i < EDIM / 4; i++) {
            float4 t = qp[i];
            t.x *= qscale; t.y *= qscale; t.z *= qscale; t.w *= qscale;
            q4[i] = t;
        }
    }

    float o[EDIM];
#pragma unroll
    for (int i = 0; i < EDIM; i++) o[i] = 0.f;
    float m = -1e30f;   // finite sentinel: avoids (-inf) - (-inf) NaN
    float l = 0.f;

    const int row_stride4 = Hz * (EDIM / 4);  // float4 stride between seq positions

    // Causal: only key tiles with start <= q0 + BM - 1
    for (int j0 = 0; j0 < q0 + BM; j0 += BN) {
        // Cooperative tile load: BN*EDIM/4 = 1024 float4, 8 per thread.
        {
            const float4* Kg =
                (const float4*)(K + ((size_t)((b * Lz + j0) * Hz + h)) * EDIM);
            const float4* Vg =
                (const float4*)(V + ((size_t)((b * Lz + j0) * Hz + h)) * EDIM);
#pragma unroll
            for (int t = 0; t < (BN * EDIM / 4) / BM; t++) {
                int idx = t * BM + threadIdx.x;
                int r = idx >> 4;        // key row within tile
                int c = idx & 15;        // float4 within row
                ((float4*)Ks[r])[c] = Kg[r * row_stride4 + c];
                ((float4*)Vs[r])[c] = Vg[r * row_stride4 + c];
            }
        }
        __syncthreads();

#pragma unroll 1
        for (int c0 = 0; c0 < BN; c0 += CH) {
            const int jbase = j0 + c0;
            if (jbase > row) break;   // rest of tile fully masked for this row

            // ---- scores: s[jj] = (q . k_j) in log2 domain ----
            float s[CH];
#pragma unroll
            for (int jj = 0; jj < CH; jj++) {
                float a0 = 0.f, a1 = 0.f, a2 = 0.f, a3 = 0.f;
                const float4* kr = (const float4*)Ks[c0 + jj];
#pragma unroll
                for (int i = 0; i < EDIM / 4; i++) {
                    float4 k = kr[i];   // broadcast LDS.128 (conflict-free)
                    a0 += q4[i].x * k.x;
                    a1 += q4[i].y * k.y;
                    a2 += q4[i].z * k.z;
                    a3 += q4[i].w * k.w;
                }
                s[jj] = (a0 + a1) + (a2 + a3);
            }

            // ---- causal mask (only the diagonal-straddling chunk diverges) ----
            if (jbase + CH - 1 > row) {
#pragma unroll
                for (int jj = 0; jj < CH; jj++)
                    if (jbase + jj > row) s[jj] = -1e30f;
            }

            // ---- online softmax update ----
            float cmax = s[0];
#pragma unroll
            for (int jj = 1; jj < CH; jj++) cmax = fmaxf(cmax, s[jj]);
            const float mnew  = fmaxf(m, cmax);
            const float alpha = exp2f(m - mnew);
            float psum = 0.f;
#pragma unroll
            for (int jj = 0; jj < CH; jj++) {
                s[jj] = exp2f(s[jj] - mnew);
                psum += s[jj];
            }
            l = l * alpha + psum;
            m = mnew;

#pragma unroll
            for (int i = 0; i < EDIM; i++) o[i] *= alpha;

            // ---- PV accumulate ----
#pragma unroll
            for (int jj = 0; jj < CH; jj++) {
                const float p = s[jj];
                const float4* vr = (const float4*)Vs[c0 + jj];
#pragma unroll
                for (int i = 0; i < EDIM / 4; i++) {
                    float4 v = vr[i];   // broadcast LDS.128
                    o[4 * i + 0] += p * v.x;
                    o[4 * i + 1] += p * v.y;
                    o[4 * i + 2] += p * v.z;
                    o[4 * i + 3] += p * v.w;
                }
            }
        }
        __syncthreads();
    }

    // ---- finalize & store (64 contiguous floats per row) ----
    const float inv = 1.f / l;
    float4* op = (float4*)(O + ((size_t)((b * Lz + row) * Hz + h)) * EDIM);
#pragma unroll
    for (int i = 0; i < EDIM / 4; i++) {
        float4 t;
        t.x = o[4 * i + 0] * inv;
        t.y = o[4 * i + 1] * inv;
        t.z = o[4 * i + 2] * inv;
        t.w = o[4 * i + 3] * inv;
        op[i] = t;
    }
}

extern "C" void kernel_launch(void* const* d_in, const int* in_sizes, int n_in,
                              void* d_out, int out_size) {
    const float* Q = (const float*)d_in[0];
    const float* K = (const float*)d_in[1];
    const float* V = (const float*)d_in[2];
    float* O = (float*)d_out;

    dim3 grid(Lz / BM, Bz * Hz);   // (16, 32) = 512 CTAs
    fullattn_kernel<<<grid, BM>>>(Q, K, V, O);
}

// round 11
// speedup vs baseline: 1.2170x; 1.2170x over previous
#include <cuda_runtime.h>

// FullAttention (causal) — B=2, L=2048, H=16, E=D=64, fp32.
// R5: split each query row across 2 threads (32 dims each) to cut registers
// (189 -> ~110) and double resident warps (8 -> 16 per SM). Half-dots are
// combined with one shfl.xor(16); chunk-loop break is warp-uniform so the
// shuffle is convergence-safe. Smem rows padded +4 floats so the two
// half-row addresses (128B apart) hit different banks. blockIdx.x reversed
// so heavy causal CTAs launch first.

#define BM   128    // query rows per CTA
#define BN   64     // keys staged in SMEM per tile
#define CH   16     // keys per register-resident softmax chunk
#define EDIM 64
#define HALF 32     // dims per thread
#define SROW (EDIM + 4)   // padded smem row (floats)

#define Bz 2
#define Lz 2048
#define Hz 16

__global__ __launch_bounds__(256, 2) void fullattn_kernel(
    const float* __restrict__ Q, const float* __restrict__ K,
    const float* __restrict__ V, float* __restrict__ O)
{
    __shared__ float Ks[BN * SROW];
    __shared__ float Vs[BN * SROW];

    const int tid  = threadIdx.x;
    const int bh   = blockIdx.y;          // b*Hz + h
    const int b    = bh >> 4;
    const int h    = bh & 15;
    // Reversed mapping: low bid -> high q0 (heavy CTAs first, light tail)
    const int q0   = ((int)gridDim.x - 1 - (int)blockIdx.x) * BM;

    const int w    = tid >> 5;            // warp 0..7
    const int lane = tid & 31;
    const int rw   = lane & 15;           // row-within-warp 0..15
    const int half = lane >> 4;           // 0 or 1: which 32 dims
    const int row  = q0 + (w << 4) + rw;  // this thread's query row
    const int wrow_max = q0 + (w << 4) + 15;  // warp-uniform causal bound

    // half1 dims d in [32,64) live at smem col d+4 (bank shift of 4)
    const int scol_half = half * (HALF + 4);

    // 1/sqrt(64) * log2(e): softmax in base-2 (MUFU.EX2)
    const float qscale = 0.125f * 1.44269504088896340736f;

    // Load + pre-scale this thread's 32 q dims
    float4 q4[HALF / 4];
    {
        const float4* qp = (const float4*)(
            Q + ((size_t)((b * Lz + row) * Hz + h)) * EDIM + half * HALF);
#pragma unroll
        for (int i = 0; i < HALF / 4; i++) {
            float4 t = qp[i];
            t.x *= qscale; t.y *= qscale; t.z *= qscale; t.w *= qscale;
            q4[i] = t;
        }
    }

    float o[HALF];
#pragma unroll
    for (int i = 0; i < HALF; i++) o[i] = 0.f;
    float m = -1e30f;   // finite sentinel
    float l = 0.f;

    const int rs4 = Hz * (EDIM / 4);   // float4 stride between seq positions

    for (int j0 = 0; j0 < q0 + BM; j0 += BN) {
        // Cooperative tile load: 1024 float4 per array, 4 per thread.
        {
            const float4* Kg =
                (const float4*)(K + ((size_t)((b * Lz + j0) * Hz + h)) * EDIM);
            const float4* Vg =
                (const float4*)(V + ((size_t)((b * Lz + j0) * Hz + h)) * EDIM);
#pragma unroll
            for (int t = 0; t < (BN * EDIM / 4) / 256; t++) {
                int idx = t * 256 + tid;
                int r = idx >> 4;          // key row in tile
                int c = idx & 15;          // float4 within row
                int sc = c * 4 + ((c >= 8) ? 4 : 0);   // padded col (floats)
                *(float4*)&Ks[r * SROW + sc] = Kg[r * rs4 + c];
                *(float4*)&Vs[r * SROW + sc] = Vg[r * rs4 + c];
            }
        }
        __syncthreads();

#pragma unroll 1
        for (int c0 = 0; c0 < BN; c0 += CH) {
            const int jbase = j0 + c0;
            if (jbase > wrow_max) break;   // warp-uniform: shfl below is safe

            // ---- half-scores: s[jj] = (q_half . k_half) ----
            float s[CH];
#pragma unroll
            for (int jj = 0; jj < CH; jj++) {
                float a0 = 0.f, a1 = 0.f, a2 = 0.f, a3 = 0.f;
                const float4* kr =
                    (const float4*)&Ks[(c0 + jj) * SROW + scol_half];
#pragma unroll
                for (int i = 0; i < HALF / 4; i++) {
                    float4 k = kr[i];
                    a0 += q4[i].x * k.x;
                    a1 += q4[i].y * k.y;
                    a2 += q4[i].z * k.z;
                    a3 += q4[i].w * k.w;
                }
                s[jj] = (a0 + a1) + (a2 + a3);
            }
            // combine the two halves (partner lane = lane ^ 16, same row)
#pragma unroll
            for (int jj = 0; jj < CH; jj++)
                s[jj] += __shfl_xor_sync(0xffffffffu, s[jj], 16);

            // ---- causal mask ----
            if (jbase + CH - 1 > row) {
#pragma unroll
                for (int jj = 0; jj < CH; jj++)
                    if (jbase + jj > row) s[jj] = -1e30f;
            }

            // ---- online softmax (redundant across the 2 half-lanes) ----
            float cmax = s[0];
#pragma unroll
            for (int jj = 1; jj < CH; jj++) cmax = fmaxf(cmax, s[jj]);
            const float mnew  = fmaxf(m, cmax);
            const float alpha = exp2f(m - mnew);
            float psum = 0.f;
#pragma unroll
            for (int jj = 0; jj < CH; jj++) {
                s[jj] = exp2f(s[jj] - mnew);
                psum += s[jj];
            }
            l = l * alpha + psum;
            m = mnew;

#pragma unroll
            for (int i = 0; i < HALF; i++) o[i] *= alpha;

            // ---- PV accumulate (this thread's 32 dims) ----
#pragma unroll
            for (int jj = 0; jj < CH; jj++) {
                const float p = s[jj];
                const float4* vr =
                    (const float4*)&Vs[(c0 + jj) * SROW + scol_half];
#pragma unroll
                for (int i = 0; i < HALF / 4; i++) {
                    float4 v = vr[i];
                    o[4 * i + 0] += p * v.x;
                    o[4 * i + 1] += p * v.y;
                    o[4 * i + 2] += p * v.z;
                    o[4 * i + 3] += p * v.w;
                }
            }
        }
        __syncthreads();
    }

    // ---- finalize & store this thread's 32 contiguous output floats ----
    const float inv = 1.f / l;
    float4* op = (float4*)(
        O + ((size_t)((b * Lz + row) * Hz + h)) * EDIM + half * HALF);
#pragma unroll
    for (int i = 0; i < HALF / 4; i++) {
        float4 t;
        t.x = o[4 * i + 0] * inv;
        t.y = o[4 * i + 1] * inv;
        t.z = o[4 * i + 2] * inv;
        t.w = o[4 * i + 3] * inv;
        op[i] = t;
    }
}

extern "C" void kernel_launch(void* const* d_in, const int* in_sizes, int n_in,
                              void* d_out, int out_size) {
    const float* Q = (const float*)d_in[0];
    const float* K = (const float*)d_in[1];
    const float* V = (const float*)d_in[2];
    float* O = (float*)d_out;

    dim3 grid(Lz / BM, Bz * Hz);   // (16, 32) = 512 CTAs
    fullattn_kernel<<<grid, 256>>>(Q, K, V, O);
}